// round 11
// baseline (speedup 1.0000x reference)
#include <cuda_runtime.h>
#include <cstdint>

#define C 512
#define NBINS 256
#define RPB 4              // rows per block (2 warps per row, 256 threads)

// k thresholds for C=512: int(C/2), int(C*2/3), int(C*3/4), int(C*4/5)
#define K1 256u
#define K2 341u
#define K3 384u
#define K4 409u

// Fixed-exponent quantization: y = x + 3*2^17 has ulp = 1/32 over |x|<4.
#define OFFF 393216.0f
#define TOPB 0x48C00080u   // bits(OFFF + 4.0f)

// Monotone 32-bit key: larger float -> larger key. (Boundary elems only.)
__device__ __forceinline__ unsigned int mono_key(float x)
{
    unsigned int u = __float_as_uint(x);
    return u ^ (((unsigned int)((int)u >> 31)) | 0x80000000u);
}

// zero-byte detector: 0x80 set in each byte of t that is zero
#define ZB(t) ((((t) - 0x01010101u) & ~(t)) & 0x80808080u)

#define ROWBAR() asm volatile("bar.sync %0, 64;" :: "r"(1 + r) : "memory")

__global__ __launch_bounds__(256, 5)
void multiscale_topk_kernel(const float* __restrict__ attn,
                            const float* __restrict__ w1p,
                            const float* __restrict__ w2p,
                            const float* __restrict__ w3p,
                            const float* __restrict__ w4p,
                            float* __restrict__ out)
{
    __shared__ unsigned int       cnt[RPB][NBINS];
    __shared__ unsigned long long list[RPB][C];
    __shared__ unsigned int       listN[RPB];
    __shared__ unsigned long long Tk[RPB][4];
    __shared__ float4             part[RPB][2];

    const int tid  = threadIdx.x;
    const int lane = tid & 31;
    const int wid  = tid >> 5;
    const int r    = wid >> 1;           // row slot 0..3
    const int ws   = wid & 1;            // warp-sub within the row
    const int hl   = ws * 32 + lane;     // 0..63 within row team
    const int row  = blockIdx.x * RPB + r;
    const float* __restrict__ rp = attn + (size_t)row * C;

    // ---- phase 1: zero cnt (64 lanes x 4 bins), init, load ----
    *(uint4*)&cnt[r][hl * 4] = make_uint4(0u, 0u, 0u, 0u);
    if (hl == 0) listN[r] = 0u;
    const float w1 = __ldg(w1p), w2 = __ldg(w2p), w3 = __ldg(w3p), w4 = __ldg(w4p);

    // 8 elems / lane: float4 j = 32*ws + lane + 64*g  ->  gidx = 4*j + e
    float4 X[2];
    #pragma unroll
    for (int g = 0; g < 2; g++)
        X[g] = ((const float4*)rp)[32 * ws + lane + 64 * g];

    ROWBAR();                                  // A: cnt zeroed

    // ---- phase 2: exact-bit bins + histogram ----
    unsigned int binw[2];
    {
        const float YLO = __uint_as_float(TOPB - 255u);
        const float YHI = __uint_as_float(TOPB);
        const unsigned int sel[4] = {0u, 0x3240u, 0x3410u, 0x4210u};
        const float* xv = (const float*)X;
        #pragma unroll
        for (int g = 0; g < 2; g++) {
            unsigned int bw = 0u;
            #pragma unroll
            for (int e = 0; e < 4; e++) {
                float yc = fminf(fmaxf(xv[4 * g + e] + OFFF, YLO), YHI);
                unsigned int b = TOPB - __float_as_uint(yc);   // 0..255 exact
                bw = (e == 0) ? b : __byte_perm(bw, b, sel[e]);
                atomicAdd(&cnt[r][b], 1u);
            }
            binw[g] = bw;
        }
    }
    ROWBAR();                                  // B: histogram complete

    // ---- phase 3: per-warp redundant scan; boundary bins in registers ----
    unsigned int bk1, bk2, bk3, bk4, gg1, gg2, gg3, gg4;
    {
        unsigned int bb[4], gg[4];
        uint4 c0 = *(uint4*)&cnt[r][lane * 8];
        uint4 c1 = *(uint4*)&cnt[r][lane * 8 + 4];
        unsigned int cc[8] = {c0.x, c0.y, c0.z, c0.w, c1.x, c1.y, c1.z, c1.w};
        unsigned int tot = 0u;
        #pragma unroll
        for (int j = 0; j < 8; j++) tot += cc[j];
        unsigned int ti = tot;
        #pragma unroll
        for (int d = 1; d < 32; d <<= 1) {
            unsigned int v = __shfl_up_sync(0xffffffffu, ti, d);
            if (lane >= d) ti += v;
        }
        unsigned int run = ti - tot;
        unsigned int fnd = 0u;
        #pragma unroll
        for (int j = 0; j < 8; j++) {
            unsigned int G = run, E = run + cc[j];
            if (G < K4 && E >= K1) {
                unsigned int b = (unsigned int)(lane * 8 + j);
                if (G < K1 && E >= K1) { bb[0] = b; gg[0] = G; fnd |= 1u; }
                if (G < K2 && E >= K2) { bb[1] = b; gg[1] = G; fnd |= 2u; }
                if (G < K3 && E >= K3) { bb[2] = b; gg[2] = G; fnd |= 4u; }
                if (G < K4 && E >= K4) { bb[3] = b; gg[3] = G; fnd |= 8u; }
            }
            run = E;
        }
        // broadcast each found (bb,gg) from its finder lane to the warp
        #pragma unroll
        for (int k = 0; k < 4; k++) {
            unsigned int src = __ffs(__ballot_sync(0xffffffffu, (fnd >> k) & 1u)) - 1u;
            bb[k] = __shfl_sync(0xffffffffu, bb[k], src);
            gg[k] = __shfl_sync(0xffffffffu, gg[k], src);
        }
        bk1 = bb[0]; bk2 = bb[1]; bk3 = bb[2]; bk4 = bb[3];
        gg1 = gg[0]; gg2 = gg[1]; gg3 = gg[2]; gg4 = gg[3];
    }
    const float E1 = __uint_as_float(TOPB - bk1);
    const float E2 = __uint_as_float(TOPB - bk2);
    const float E3 = __uint_as_float(TOPB - bk3);
    const float E4 = __uint_as_float(TOPB - bk4);

    // ---- phase 4: amb detect + gather ----
    unsigned int ambm = 0u;
    {
        const unsigned int k1x4 = bk1 * 0x01010101u;
        const unsigned int k2x4 = bk2 * 0x01010101u;
        const unsigned int k3x4 = bk3 * 0x01010101u;
        const unsigned int k4x4 = bk4 * 0x01010101u;
        #pragma unroll
        for (int g = 0; g < 2; g++) {
            unsigned int w = binw[g];
            unsigned int z = ZB(w ^ k1x4) | ZB(w ^ k2x4) | ZB(w ^ k3x4) | ZB(w ^ k4x4);
            ambm |= ((((z >> 7) * 0x01020408u) >> 24) & 0xFu) << (4 * g);
        }
    }
    {
        const float* xv = (const float*)X;
        unsigned int am = ambm;
        while (am) {
            int i = __ffs(am) - 1; am &= am - 1;
            int gidx = 4 * lane + 128 * ws + 256 * (i >> 2) + (i & 3);
            unsigned int b = (binw[i >> 2] >> (8 * (i & 3))) & 255u;
            unsigned long long key = ((unsigned long long)b << 48)
                | ((unsigned long long)mono_key(xv[i]) << 16)
                | (unsigned long long)(65535u - (unsigned int)gidx);
            unsigned int pos = atomicAdd(&listN[r], 1u);
            list[r][pos] = key;
        }
    }
    ROWBAR();                                  // C: candidate list complete

    // ---- phase 5: selection across 64 lanes ----
    {
        const unsigned int M = listN[r];
        for (unsigned int j = (unsigned int)hl; j < M; j += 64u) {
            unsigned long long cj = list[r][j];
            unsigned int hb = (unsigned int)(cj >> 48);
            unsigned int g0 = (hb == bk1) ? gg1 : (hb == bk2) ? gg2
                            : (hb == bk3) ? gg3 : gg4;
            unsigned int rr = g0;
            for (unsigned int q = 0u; q < M; q++) {
                unsigned long long cq = list[r][q];
                rr += (unsigned int)((cq > cj) && ((unsigned int)(cq >> 48) == hb));
            }
            if (hb == bk1 && rr == K1 - 1u) Tk[r][0] = cj;
            if (hb == bk2 && rr == K2 - 1u) Tk[r][1] = cj;
            if (hb == bk3 && rr == K3 - 1u) Tk[r][2] = cj;
            if (hb == bk4 && rr == K4 - 1u) Tk[r][3] = cj;
        }
    }
    ROWBAR();                                  // D: thresholds ready

    // ---- phase 6: corrections (signed deltas + mask flips) ----
    float s1 = 0.f, s2 = 0.f, s3 = 0.f, s4 = 0.f;
    unsigned int f1 = 0u, f2 = 0u, f3 = 0u, f4 = 0u;
    if (ambm) {
        const unsigned long long T1 = Tk[r][0], T2 = Tk[r][1],
                                 T3 = Tk[r][2], T4 = Tk[r][3];
        const float* xv = (const float*)X;
        unsigned int am = ambm;
        while (am) {
            int i = __ffs(am) - 1; am &= am - 1;
            float x = xv[i];
            float y = x + OFFF;
            float e = __expf(x);
            int gidx = 4 * lane + 128 * ws + 256 * (i >> 2) + (i & 3);
            unsigned int b = (binw[i >> 2] >> (8 * (i & 3))) & 255u;
            unsigned long long key = ((unsigned long long)b << 48)
                | ((unsigned long long)mono_key(x) << 16)
                | (unsigned long long)(65535u - (unsigned int)gidx);
            {
                bool fp = y > E1, in = (b == bk1) ? (key >= T1) : fp;
                if (in != fp) { f1 |= 1u << i; s1 += in ? e : -e; }
            }
            {
                bool fp = y > E2, in = (b == bk2) ? (key >= T2) : fp;
                if (in != fp) { f2 |= 1u << i; s2 += in ? e : -e; }
            }
            {
                bool fp = y > E3, in = (b == bk3) ? (key >= T3) : fp;
                if (in != fp) { f3 |= 1u << i; s3 += in ? e : -e; }
            }
            {
                bool fp = y > E4, in = (b == bk4) ? (key >= T4) : fp;
                if (in != fp) { f4 |= 1u << i; s4 += in ? e : -e; }
            }
        }
    }

    // ---- phase 7: fused exp + membership sums + masks; X := exp(x) ----
    unsigned int m1 = 0u, m2 = 0u, m3 = 0u, m4 = 0u;
    {
        float* xv = (float*)X;
        #pragma unroll
        for (int i = 0; i < 8; i++) {
            float x = xv[i];
            float y = x + OFFF;
            float e = __expf(x);          // softmax shift-invariant; |x| ~ 5
            xv[i] = e;
            if (y > E1) { s1 += e; m1 |= 1u << i; }
            if (y > E2) { s2 += e; m2 |= 1u << i; }
            if (y > E3) { s3 += e; m3 |= 1u << i; }
            if (y > E4) { s4 += e; m4 |= 1u << i; }
        }
    }
    m1 ^= f1; m2 ^= f2; m3 ^= f3; m4 ^= f4;

    #pragma unroll
    for (int o = 16; o > 0; o >>= 1) {
        s1 += __shfl_xor_sync(0xffffffffu, s1, o);
        s2 += __shfl_xor_sync(0xffffffffu, s2, o);
        s3 += __shfl_xor_sync(0xffffffffu, s3, o);
        s4 += __shfl_xor_sync(0xffffffffu, s4, o);
    }
    if (lane == 0) part[r][ws] = make_float4(s1, s2, s3, s4);
    ROWBAR();                                  // E: partial sums ready

    const float4 pa = part[r][0], pb = part[r][1];
    const float q1 = __fdividef(w1, pa.x + pb.x), q2 = __fdividef(w2, pa.y + pb.y),
                q3 = __fdividef(w3, pa.z + pb.z), q4 = __fdividef(w4, pa.w + pb.w);

    // ---- phase 8: write ----
    {
        const float* ev = (const float*)X;
        float4* op = (float4*)(out + (size_t)row * C);
        #pragma unroll
        for (int g = 0; g < 2; g++) {
            float4 o4;
            float* o = (float*)&o4;
            #pragma unroll
            for (int e = 0; e < 4; e++) {
                int i = 4 * g + e;
                float coef = 0.f;
                if ((m1 >> i) & 1u) coef += q1;
                if ((m2 >> i) & 1u) coef += q2;
                if ((m3 >> i) & 1u) coef += q3;
                if ((m4 >> i) & 1u) coef += q4;
                o[e] = ev[i] * coef;
            }
            op[32 * ws + lane + 64 * g] = o4;
        }
    }
}

extern "C" void kernel_launch(void* const* d_in, const int* in_sizes, int n_in,
                              void* d_out, int out_size)
{
    const float* attn = (const float*)d_in[0];
    const float* w1   = (const float*)d_in[1];
    const float* w2   = (const float*)d_in[2];
    const float* w3   = (const float*)d_in[3];
    const float* w4   = (const float*)d_in[4];
    float* out = (float*)d_out;

    int rows   = in_sizes[0] / C;
    int blocks = rows / RPB;
    multiscale_topk_kernel<<<blocks, 256>>>(attn, w1, w2, w3, w4, out);
}

// round 12
// speedup vs baseline: 1.4292x; 1.4292x over previous
#include <cuda_runtime.h>
#include <cstdint>

#define C 512
#define NBINS 256
#define RPB 8
#define LIST_CAP 512   // = C: boundary bins can never overflow

// k thresholds for C=512: int(C/2), int(C*2/3), int(C*3/4), int(C*4/5)
#define K1 256u
#define K2 341u
#define K3 384u
#define K4 409u

// Fixed-exponent quantization: y = x + 3*2^17 has ulp = 1/32 over |x|<4.
#define OFFF 393216.0f
#define TOPB 0x48C00080u   // bits(OFFF + 4.0f)

// Monotone 32-bit key: larger float -> larger key. (Boundary elems only.)
__device__ __forceinline__ unsigned int mono_key(float x)
{
    unsigned int u = __float_as_uint(x);
    return u ^ (((unsigned int)((int)u >> 31)) | 0x80000000u);
}

// zero-byte detector: 0x80 set in each byte of t that is zero
#define ZB(t) ((((t) - 0x01010101u) & ~(t)) & 0x80808080u)

__global__ __launch_bounds__(32 * RPB, 4)
void multiscale_topk_kernel(const float* __restrict__ attn,
                            const float* __restrict__ w1p,
                            const float* __restrict__ w2p,
                            const float* __restrict__ w3p,
                            const float* __restrict__ w4p,
                            float* __restrict__ out)
{
    __shared__ unsigned int       cnt[RPB][NBINS];
    __shared__ unsigned long long list[RPB][LIST_CAP];
    __shared__ unsigned int       listN[RPB];
    __shared__ uint4              bbs[RPB];          // per k: (bin<<16) | G
    __shared__ unsigned long long Tk[RPB][4];        // 64-bit threshold keys

    const int lane = threadIdx.x & 31;
    const int wrow = threadIdx.x >> 5;
    const int row  = blockIdx.x * RPB + wrow;
    const float* __restrict__ rp = attn + (size_t)row * C;

    const float YLO = __uint_as_float(TOPB - 255u);
    const float YHI = __uint_as_float(TOPB);

    // ---- init ----
    {
        uint4 z = make_uint4(0u, 0u, 0u, 0u);
        *(uint4*)&cnt[wrow][lane * 8]     = z;
        *(uint4*)&cnt[wrow][lane * 8 + 4] = z;
        if (lane == 0) listN[wrow] = 0u;
    }
    const float w1 = __ldg(w1p), w2 = __ldg(w2p), w3 = __ldg(w3p), w4 = __ldg(w4p);

    // ---- load 16 elems / lane (coalesced float4) ----
    float4 X[4];
    #pragma unroll
    for (int g = 0; g < 4; g++)
        X[g] = ((const float4*)rp)[lane + 32 * g];

    __syncwarp();

    // ---- pass A: float-clamped exact-bit bins + count histogram ----
    unsigned int binw[4];
    {
        const unsigned int sel[4] = {0u, 0x3240u, 0x3410u, 0x4210u};
        const float* xv = (const float*)X;
        #pragma unroll
        for (int g = 0; g < 4; g++) {
            unsigned int bw = 0u;
            #pragma unroll
            for (int e = 0; e < 4; e++) {
                float yc = fminf(fmaxf(xv[4 * g + e] + OFFF, YLO), YHI);
                unsigned int b = TOPB - __float_as_uint(yc);   // 0..255 exact
                bw = (e == 0) ? b : __byte_perm(bw, b, sel[e]);
                atomicAdd(&cnt[wrow][b], 1u);
            }
            binw[g] = bw;
        }
    }
    __syncwarp();

    // ---- scan 256 bins; locate the 4 boundary bins (G < k <= G+cnt) ----
    {
        uint4 c0 = *(uint4*)&cnt[wrow][lane * 8];
        uint4 c1 = *(uint4*)&cnt[wrow][lane * 8 + 4];
        unsigned int cc[8] = {c0.x, c0.y, c0.z, c0.w, c1.x, c1.y, c1.z, c1.w};
        unsigned int tot = 0u;
        #pragma unroll
        for (int j = 0; j < 8; j++) tot += cc[j];
        unsigned int ti = tot;
        #pragma unroll
        for (int d = 1; d < 32; d <<= 1) {
            unsigned int v = __shfl_up_sync(0xffffffffu, ti, d);
            if (lane >= d) ti += v;
        }
        unsigned int run = ti - tot;               // exclusive prefix
        #pragma unroll
        for (int j = 0; j < 8; j++) {
            unsigned int G = run, E = run + cc[j];
            if (G < K4 && E >= K1) {
                unsigned int w = ((unsigned int)(lane * 8 + j) << 16) | G;
                if (G < K1 && E >= K1) bbs[wrow].x = w;
                if (G < K2 && E >= K2) bbs[wrow].y = w;
                if (G < K3 && E >= K3) bbs[wrow].z = w;
                if (G < K4 && E >= K4) bbs[wrow].w = w;
            }
            run = E;
        }
    }
    __syncwarp();

    const uint4 B = bbs[wrow];
    const unsigned int bk1 = B.x >> 16, bk2 = B.y >> 16, bk3 = B.z >> 16, bk4 = B.w >> 16;
    const unsigned int gg1 = B.x & 0xFFFFu, gg2 = B.y & 0xFFFFu,
                       gg3 = B.z & 0xFFFFu, gg4 = B.w & 0xFFFFu;
    // Fast-path edges: bin < b_k  <=>  y > E_k  (exact; bin == b_k is amb)
    const float E1 = __uint_as_float(TOPB - bk1);
    const float E2 = __uint_as_float(TOPB - bk2);
    const float E3 = __uint_as_float(TOPB - bk3);
    const float E4 = __uint_as_float(TOPB - bk4);
    // exp-domain edges for the write pass: non-amb elems are >= 1/64 in x from
    // the bin edge, so e vs F_k has >= 1.5% relative margin (>> MUFU error).
    const float F1 = __expf(E1 - OFFF);
    const float F2 = __expf(E2 - OFFF);
    const float F3 = __expf(E3 - OFFF);
    const float F4 = __expf(E4 - OFFF);

    // ---- vectorized amb detection (bin byte == some boundary bin) ----
    unsigned int ambm = 0u;
    {
        const unsigned int k1x4 = bk1 * 0x01010101u;
        const unsigned int k2x4 = bk2 * 0x01010101u;
        const unsigned int k3x4 = bk3 * 0x01010101u;
        const unsigned int k4x4 = bk4 * 0x01010101u;
        #pragma unroll
        for (int g = 0; g < 4; g++) {
            unsigned int w = binw[g];
            unsigned int z = ZB(w ^ k1x4) | ZB(w ^ k2x4) | ZB(w ^ k3x4) | ZB(w ^ k4x4);
            ambm |= ((((z >> 7) * 0x01020408u) >> 24) & 0xFu) << (4 * g);
        }
    }

    // ---- gather boundary candidates (x live in X) ----
    {
        const float* xv = (const float*)X;
        unsigned int am = ambm;
        while (am) {
            int i = __ffs(am) - 1; am &= am - 1;
            int gidx = 4 * lane + 128 * (i >> 2) + (i & 3);
            unsigned int b = (binw[i >> 2] >> (8 * (i & 3))) & 255u;
            unsigned long long key = ((unsigned long long)b << 48)
                | ((unsigned long long)mono_key(xv[i]) << 16)
                | (unsigned long long)(65535u - (unsigned int)gidx);
            unsigned int pos = atomicAdd(&listN[wrow], 1u);
            list[wrow][pos] = key;
        }
    }
    __syncwarp();

    // ---- selection: exact k-th largest key per boundary bin ----
    {
        const unsigned int M = listN[wrow];
        for (unsigned int j = lane; j < M; j += 32) {
            unsigned long long cj = list[wrow][j];
            unsigned int hb = (unsigned int)(cj >> 48);
            unsigned int g0 = (hb == bk1) ? gg1 : (hb == bk2) ? gg2
                            : (hb == bk3) ? gg3 : gg4;
            unsigned int r = g0;
            for (unsigned int q = 0u; q < M; q++) {
                unsigned long long cq = list[wrow][q];
                r += (unsigned int)((cq > cj) && ((unsigned int)(cq >> 48) == hb));
            }
            if (hb == bk1 && r == K1 - 1u) Tk[wrow][0] = cj;
            if (hb == bk2 && r == K2 - 1u) Tk[wrow][1] = cj;
            if (hb == bk3 && r == K3 - 1u) Tk[wrow][2] = cj;
            if (hb == bk4 && r == K4 - 1u) Tk[wrow][3] = cj;
        }
    }
    __syncwarp();

    // ---- corrections for ambiguous elems: signed sum deltas vs the y-compare
    //      fast path, plus exact membership bits (om) for the post-store fix ----
    float s1 = 0.f, s2 = 0.f, s3 = 0.f, s4 = 0.f;
    unsigned int om1 = 0u, om2 = 0u, om3 = 0u, om4 = 0u;
    if (ambm) {
        const unsigned long long T1 = Tk[wrow][0], T2 = Tk[wrow][1],
                                 T3 = Tk[wrow][2], T4 = Tk[wrow][3];
        const float* xv = (const float*)X;
        unsigned int am = ambm;
        while (am) {
            int i = __ffs(am) - 1; am &= am - 1;
            float x = xv[i];
            float y = x + OFFF;          // unclamped: matches fused pass bit-exactly
            float e = __expf(x);
            int gidx = 4 * lane + 128 * (i >> 2) + (i & 3);
            unsigned int b = (binw[i >> 2] >> (8 * (i & 3))) & 255u;
            unsigned long long key = ((unsigned long long)b << 48)
                | ((unsigned long long)mono_key(x) << 16)
                | (unsigned long long)(65535u - (unsigned int)gidx);
            {
                bool fp = y > E1, in = (b == bk1) ? (key >= T1) : fp;
                if (in) om1 |= 1u << i;
                if (in != fp) s1 += in ? e : -e;
            }
            {
                bool fp = y > E2, in = (b == bk2) ? (key >= T2) : fp;
                if (in) om2 |= 1u << i;
                if (in != fp) s2 += in ? e : -e;
            }
            {
                bool fp = y > E3, in = (b == bk3) ? (key >= T3) : fp;
                if (in) om3 |= 1u << i;
                if (in != fp) s3 += in ? e : -e;
            }
            {
                bool fp = y > E4, in = (b == bk4) ? (key >= T4) : fp;
                if (in) om4 |= 1u << i;
                if (in != fp) s4 += in ? e : -e;
            }
        }
    }

    // ---- fused pass: exp + membership sums (no masks); X := exp(x) ----
    {
        float* xv = (float*)X;
        #pragma unroll
        for (int i = 0; i < 16; i++) {
            float x = xv[i];
            float y = x + OFFF;
            float e = __expf(x);          // softmax shift-invariant; |x| ~ 5
            xv[i] = e;
            if (y > E1) s1 += e;
            if (y > E2) s2 += e;
            if (y > E3) s3 += e;
            if (y > E4) s4 += e;
        }
    }
    #pragma unroll
    for (int o = 16; o > 0; o >>= 1) {
        s1 += __shfl_xor_sync(0xffffffffu, s1, o);
        s2 += __shfl_xor_sync(0xffffffffu, s2, o);
        s3 += __shfl_xor_sync(0xffffffffu, s3, o);
        s4 += __shfl_xor_sync(0xffffffffu, s4, o);
    }
    const float q1 = __fdividef(w1, s1), q2 = __fdividef(w2, s2),
                q3 = __fdividef(w3, s3), q4 = __fdividef(w4, s4);

    // ---- write: exp-domain compares (exact for all non-amb elements) ----
    {
        const float* ev = (const float*)X;
        float4* op = (float4*)(out + (size_t)row * C);
        #pragma unroll
        for (int g = 0; g < 4; g++) {
            float4 o4;
            float* o = (float*)&o4;
            #pragma unroll
            for (int e = 0; e < 4; e++) {
                float ee = ev[4 * g + e];
                float coef = 0.f;
                if (ee > F1) coef += q1;
                if (ee > F2) coef += q2;
                if (ee > F3) coef += q3;
                if (ee > F4) coef += q4;
                o[e] = ee * coef;
            }
            op[lane + 32 * g] = o4;
        }
    }

    // ---- post-store exact fix for ambiguous elems (~2/thread; same-thread
    //      same-address STG ordering is program order) ----
    if (ambm) {
        const float* ev = (const float*)X;
        float* ob = out + (size_t)row * C;
        unsigned int am = ambm;
        while (am) {
            int i = __ffs(am) - 1; am &= am - 1;
            int gidx = 4 * lane + 128 * (i >> 2) + (i & 3);
            float cf = 0.f;
            if ((om1 >> i) & 1u) cf += q1;
            if ((om2 >> i) & 1u) cf += q2;
            if ((om3 >> i) & 1u) cf += q3;
            if ((om4 >> i) & 1u) cf += q4;
            ob[gidx] = ev[i] * cf;
        }
    }
}

extern "C" void kernel_launch(void* const* d_in, const int* in_sizes, int n_in,
                              void* d_out, int out_size)
{
    const float* attn = (const float*)d_in[0];
    const float* w1   = (const float*)d_in[1];
    const float* w2   = (const float*)d_in[2];
    const float* w3   = (const float*)d_in[3];
    const float* w4   = (const float*)d_in[4];
    float* out = (float*)d_out;

    int rows   = in_sizes[0] / C;
    int blocks = rows / RPB;
    multiscale_topk_kernel<<<blocks, 32 * RPB>>>(attn, w1, w2, w3, w4, out);
}

// round 13
// speedup vs baseline: 1.6411x; 1.1483x over previous
#include <cuda_runtime.h>
#include <cstdint>

#define C 512
#define NBINS 256
#define RPB 8
#define LIST_CAP 512   // = C: boundary bins can never overflow

// k thresholds for C=512: int(C/2), int(C*2/3), int(C*3/4), int(C*4/5)
#define K1 256u
#define K2 341u
#define K3 384u
#define K4 409u

// Fixed-exponent quantization: y = x + 3*2^17 has ulp = 1/32 over |x|<4.
#define OFFF 393216.0f
#define TOPB 0x48C00080u   // bits(OFFF + 4.0f)

// Monotone 32-bit key: larger float -> larger key. (Boundary elems only.)
__device__ __forceinline__ unsigned int mono_key(float x)
{
    unsigned int u = __float_as_uint(x);
    return u ^ (((unsigned int)((int)u >> 31)) | 0x80000000u);
}

// zero-byte detector: 0x80 set in each byte of t that is zero
#define ZB(t) ((((t) - 0x01010101u) & ~(t)) & 0x80808080u)

__global__ __launch_bounds__(32 * RPB, 4)
void multiscale_topk_kernel(const float* __restrict__ attn,
                            const float* __restrict__ w1p,
                            const float* __restrict__ w2p,
                            const float* __restrict__ w3p,
                            const float* __restrict__ w4p,
                            float* __restrict__ out)
{
    __shared__ unsigned int       cnt[RPB][NBINS];
    __shared__ unsigned long long list[RPB][LIST_CAP];
    __shared__ unsigned int       listN[RPB];
    __shared__ uint4              bbs[RPB];          // per k: (bin<<16) | G
    __shared__ unsigned char      ovr[RPB][C];       // membership bits per amb elem

    const int lane = threadIdx.x & 31;
    const int wrow = threadIdx.x >> 5;
    const int row  = blockIdx.x * RPB + wrow;
    const float* __restrict__ rp = attn + (size_t)row * C;

    const float YLO = __uint_as_float(TOPB - 255u);
    const float YHI = __uint_as_float(TOPB);

    // ---- init ----
    {
        uint4 z = make_uint4(0u, 0u, 0u, 0u);
        *(uint4*)&cnt[wrow][lane * 8]     = z;
        *(uint4*)&cnt[wrow][lane * 8 + 4] = z;
        if (lane == 0) listN[wrow] = 0u;
    }
    const float w1 = __ldg(w1p), w2 = __ldg(w2p), w3 = __ldg(w3p), w4 = __ldg(w4p);

    // ---- load 16 elems / lane (coalesced float4) ----
    float4 X[4];
    #pragma unroll
    for (int g = 0; g < 4; g++)
        X[g] = ((const float4*)rp)[lane + 32 * g];

    __syncwarp();

    // ---- pass A: float-clamped exact-bit bins + count histogram ----
    unsigned int binw[4];
    {
        const unsigned int sel[4] = {0u, 0x3240u, 0x3410u, 0x4210u};
        const float* xv = (const float*)X;
        #pragma unroll
        for (int g = 0; g < 4; g++) {
            unsigned int bw = 0u;
            #pragma unroll
            for (int e = 0; e < 4; e++) {
                float yc = fminf(fmaxf(xv[4 * g + e] + OFFF, YLO), YHI);
                unsigned int b = TOPB - __float_as_uint(yc);   // 0..255 exact
                bw = (e == 0) ? b : __byte_perm(bw, b, sel[e]);
                atomicAdd(&cnt[wrow][b], 1u);
            }
            binw[g] = bw;
        }
    }
    __syncwarp();

    // ---- scan 256 bins; locate the 4 boundary bins (G < k <= G+cnt) ----
    {
        uint4 c0 = *(uint4*)&cnt[wrow][lane * 8];
        uint4 c1 = *(uint4*)&cnt[wrow][lane * 8 + 4];
        unsigned int cc[8] = {c0.x, c0.y, c0.z, c0.w, c1.x, c1.y, c1.z, c1.w};
        unsigned int tot = 0u;
        #pragma unroll
        for (int j = 0; j < 8; j++) tot += cc[j];
        unsigned int ti = tot;
        #pragma unroll
        for (int d = 1; d < 32; d <<= 1) {
            unsigned int v = __shfl_up_sync(0xffffffffu, ti, d);
            if (lane >= d) ti += v;
        }
        unsigned int run = ti - tot;               // exclusive prefix
        #pragma unroll
        for (int j = 0; j < 8; j++) {
            unsigned int G = run, E = run + cc[j];
            if (G < K4 && E >= K1) {
                unsigned int w = ((unsigned int)(lane * 8 + j) << 16) | G;
                if (G < K1 && E >= K1) bbs[wrow].x = w;
                if (G < K2 && E >= K2) bbs[wrow].y = w;
                if (G < K3 && E >= K3) bbs[wrow].z = w;
                if (G < K4 && E >= K4) bbs[wrow].w = w;
            }
            run = E;
        }
    }
    __syncwarp();

    const uint4 B = bbs[wrow];
    const unsigned int bk1 = B.x >> 16, bk2 = B.y >> 16, bk3 = B.z >> 16, bk4 = B.w >> 16;
    const unsigned int gg1 = B.x & 0xFFFFu, gg2 = B.y & 0xFFFFu,
                       gg3 = B.z & 0xFFFFu, gg4 = B.w & 0xFFFFu;
    // Fast-path edges: bin < b_k  <=>  y > E_k  (exact; bin == b_k is amb)
    const float E1 = __uint_as_float(TOPB - bk1);
    const float E2 = __uint_as_float(TOPB - bk2);
    const float E3 = __uint_as_float(TOPB - bk3);
    const float E4 = __uint_as_float(TOPB - bk4);
    // exp-domain edges for the write pass: non-amb elems are >= 1/64 in x from
    // the bin edge, so e vs F_k has >= 1.5% relative margin (>> MUFU error).
    const float F1 = __expf(E1 - OFFF);
    const float F2 = __expf(E2 - OFFF);
    const float F3 = __expf(E3 - OFFF);
    const float F4 = __expf(E4 - OFFF);

    // ---- vectorized amb detection (bin byte == some boundary bin) ----
    unsigned int ambm = 0u;
    {
        const unsigned int k1x4 = bk1 * 0x01010101u;
        const unsigned int k2x4 = bk2 * 0x01010101u;
        const unsigned int k3x4 = bk3 * 0x01010101u;
        const unsigned int k4x4 = bk4 * 0x01010101u;
        #pragma unroll
        for (int g = 0; g < 4; g++) {
            unsigned int w = binw[g];
            unsigned int z = ZB(w ^ k1x4) | ZB(w ^ k2x4) | ZB(w ^ k3x4) | ZB(w ^ k4x4);
            ambm |= ((((z >> 7) * 0x01020408u) >> 24) & 0xFu) << (4 * g);
        }
    }

    // ---- gather boundary candidates (x live in X) ----
    {
        const float* xv = (const float*)X;
        unsigned int am = ambm;
        while (am) {
            int i = __ffs(am) - 1; am &= am - 1;
            int gidx = 4 * lane + 128 * (i >> 2) + (i & 3);
            unsigned int b = (binw[i >> 2] >> (8 * (i & 3))) & 255u;
            unsigned long long key = ((unsigned long long)b << 48)
                | ((unsigned long long)mono_key(xv[i]) << 16)
                | (unsigned long long)(65535u - (unsigned int)gidx);
            unsigned int pos = atomicAdd(&listN[wrow], 1u);
            list[wrow][pos] = key;
        }
    }
    __syncwarp();

    // ---- selection: exact rank per candidate -> membership bits + sum deltas.
    //      No threshold keys, no separate correction pass. ----
    float s1 = 0.f, s2 = 0.f, s3 = 0.f, s4 = 0.f;
    {
        const unsigned int M = listN[wrow];
        for (unsigned int j = lane; j < M; j += 32) {
            unsigned long long cj = list[wrow][j];
            unsigned int hb = (unsigned int)(cj >> 48);
            unsigned int g0 = (hb == bk1) ? gg1 : (hb == bk2) ? gg2
                            : (hb == bk3) ? gg3 : gg4;
            unsigned int r = g0;
            for (unsigned int q = 0u; q < M; q++) {
                unsigned long long cq = list[wrow][q];
                r += (unsigned int)((cq > cj) && ((unsigned int)(cq >> 48) == hb));
            }
            // recover x and exp from the key (exact bit inverse of mono_key)
            unsigned int mk = (unsigned int)(cj >> 16);
            float x = __uint_as_float((mk & 0x80000000u) ? (mk & 0x7FFFFFFFu) : ~mk);
            float e = __expf(x);
            // full membership for all 4 masks from (hb, r)
            bool i1 = (hb < bk1) | ((hb == bk1) & (r < K1));
            bool i2 = (hb < bk2) | ((hb == bk2) & (r < K2));
            bool i3 = (hb < bk3) | ((hb == bk3) & (r < K3));
            bool i4 = (hb < bk4) | ((hb == bk4) & (r < K4));
            // sum deltas only where the fused fast path (y > E_k) misses:
            if ((hb == bk1) & (r < K1)) s1 += e;
            if ((hb == bk2) & (r < K2)) s2 += e;
            if ((hb == bk3) & (r < K3)) s3 += e;
            if ((hb == bk4) & (r < K4)) s4 += e;
            unsigned int gidx = 65535u - (unsigned int)(cj & 0xFFFFu);
            ovr[wrow][gidx] = (unsigned char)((unsigned)i1 | ((unsigned)i2 << 1)
                            | ((unsigned)i3 << 2) | ((unsigned)i4 << 3));
        }
    }
    __syncwarp();

    // ---- fused pass: exp + membership sums (no masks); X := exp(x) ----
    {
        float* xv = (float*)X;
        #pragma unroll
        for (int i = 0; i < 16; i++) {
            float x = xv[i];
            float y = x + OFFF;
            float e = __expf(x);          // softmax shift-invariant; |x| ~ 5
            xv[i] = e;
            if (y > E1) s1 += e;
            if (y > E2) s2 += e;
            if (y > E3) s3 += e;
            if (y > E4) s4 += e;
        }
    }
    #pragma unroll
    for (int o = 16; o > 0; o >>= 1) {
        s1 += __shfl_xor_sync(0xffffffffu, s1, o);
        s2 += __shfl_xor_sync(0xffffffffu, s2, o);
        s3 += __shfl_xor_sync(0xffffffffu, s3, o);
        s4 += __shfl_xor_sync(0xffffffffu, s4, o);
    }
    const float q1 = __fdividef(w1, s1), q2 = __fdividef(w2, s2),
                q3 = __fdividef(w3, s3), q4 = __fdividef(w4, s4);

    // ---- write: exp-domain compares (exact for all non-amb elements) ----
    {
        const float* ev = (const float*)X;
        float4* op = (float4*)(out + (size_t)row * C);
        #pragma unroll
        for (int g = 0; g < 4; g++) {
            float4 o4;
            float* o = (float*)&o4;
            #pragma unroll
            for (int e = 0; e < 4; e++) {
                float ee = ev[4 * g + e];
                float coef = 0.f;
                if (ee > F1) coef += q1;
                if (ee > F2) coef += q2;
                if (ee > F3) coef += q3;
                if (ee > F4) coef += q4;
                o[e] = ee * coef;
            }
            op[lane + 32 * g] = o4;
        }
    }

    // ---- post-store exact fix for ambiguous elems (1 LDS byte each;
    //      same-thread same-address STG ordering is program order) ----
    if (ambm) {
        const float* ev = (const float*)X;
        float* ob = out + (size_t)row * C;
        unsigned int am = ambm;
        while (am) {
            int i = __ffs(am) - 1; am &= am - 1;
            int gidx = 4 * lane + 128 * (i >> 2) + (i & 3);
            unsigned int bits = ovr[wrow][gidx];
            float cf = 0.f;
            if (bits & 1u) cf += q1;
            if (bits & 2u) cf += q2;
            if (bits & 4u) cf += q3;
            if (bits & 8u) cf += q4;
            ob[gidx] = ev[i] * cf;
        }
    }
}

extern "C" void kernel_launch(void* const* d_in, const int* in_sizes, int n_in,
                              void* d_out, int out_size)
{
    const float* attn = (const float*)d_in[0];
    const float* w1   = (const float*)d_in[1];
    const float* w2   = (const float*)d_in[2];
    const float* w3   = (const float*)d_in[3];
    const float* w4   = (const float*)d_in[4];
    float* out = (float*)d_out;

    int rows   = in_sizes[0] / C;
    int blocks = rows / RPB;
    multiscale_topk_kernel<<<blocks, 32 * RPB>>>(attn, w1, w2, w3, w4, out);
}

// round 14
// speedup vs baseline: 1.9878x; 1.2112x over previous
#include <cuda_runtime.h>
#include <cstdint>

#define C 512
#define NBINS 256
#define RPB 8
#define LIST_CAP 512   // = C: boundary bins can never overflow

// k thresholds for C=512: int(C/2), int(C*2/3), int(C*3/4), int(C*4/5)
#define K1 256u
#define K2 341u
#define K3 384u
#define K4 409u

// Fixed-exponent quantization: y = x + 1.5*2^16 has ulp = 1/128.
// 256 bins cover x in [-1.4921875, 0.5); all 4 rank boundaries for this
// problem sit deep inside. Clamped tails -> bins 0/255 (exactness does not
// depend on this: bin==boundary-bin elements always go through exact ranks).
#define OFFF 98304.0f
#define TOPB 0x47C00040u   // bits(98304.5f)

// Monotone 32-bit key: larger float -> larger key. (Boundary elems only.)
__device__ __forceinline__ unsigned int mono_key(float x)
{
    unsigned int u = __float_as_uint(x);
    return u ^ (((unsigned int)((int)u >> 31)) | 0x80000000u);
}

// zero-byte detector: 0x80 set in each byte of t that is zero
#define ZB(t) ((((t) - 0x01010101u) & ~(t)) & 0x80808080u)

__global__ __launch_bounds__(32 * RPB, 4)
void multiscale_topk_kernel(const float* __restrict__ attn,
                            const float* __restrict__ w1p,
                            const float* __restrict__ w2p,
                            const float* __restrict__ w3p,
                            const float* __restrict__ w4p,
                            float* __restrict__ out)
{
    __shared__ unsigned int       cnt[RPB][NBINS];
    __shared__ unsigned long long list[RPB][LIST_CAP];
    __shared__ unsigned int       listN[RPB];
    __shared__ uint4              bbs[RPB];          // per k: (bin<<16) | G
    __shared__ unsigned char      ovr[RPB][C];       // membership bits per amb elem

    const int lane = threadIdx.x & 31;
    const int wrow = threadIdx.x >> 5;
    const int row  = blockIdx.x * RPB + wrow;
    const float* __restrict__ rp = attn + (size_t)row * C;

    const float YLO = __uint_as_float(TOPB - 255u);
    const float YHI = __uint_as_float(TOPB);

    // ---- init ----
    {
        uint4 z = make_uint4(0u, 0u, 0u, 0u);
        *(uint4*)&cnt[wrow][lane * 8]     = z;
        *(uint4*)&cnt[wrow][lane * 8 + 4] = z;
        if (lane == 0) listN[wrow] = 0u;
    }
    const float w1 = __ldg(w1p), w2 = __ldg(w2p), w3 = __ldg(w3p), w4 = __ldg(w4p);

    // ---- load 16 elems / lane (coalesced float4) ----
    float4 X[4];
    #pragma unroll
    for (int g = 0; g < 4; g++)
        X[g] = ((const float4*)rp)[lane + 32 * g];

    __syncwarp();

    // ---- pass A: float-clamped exact-bit bins + count histogram ----
    unsigned int binw[4];
    {
        const unsigned int sel[4] = {0u, 0x3240u, 0x3410u, 0x4210u};
        const float* xv = (const float*)X;
        #pragma unroll
        for (int g = 0; g < 4; g++) {
            unsigned int bw = 0u;
            #pragma unroll
            for (int e = 0; e < 4; e++) {
                float yc = fminf(fmaxf(xv[4 * g + e] + OFFF, YLO), YHI);
                unsigned int b = TOPB - __float_as_uint(yc);   // 0..255 exact
                bw = (e == 0) ? b : __byte_perm(bw, b, sel[e]);
                atomicAdd(&cnt[wrow][b], 1u);
            }
            binw[g] = bw;
        }
    }
    __syncwarp();

    // ---- scan 256 bins; locate the 4 boundary bins (G < k <= G+cnt) ----
    {
        uint4 c0 = *(uint4*)&cnt[wrow][lane * 8];
        uint4 c1 = *(uint4*)&cnt[wrow][lane * 8 + 4];
        unsigned int cc[8] = {c0.x, c0.y, c0.z, c0.w, c1.x, c1.y, c1.z, c1.w};
        unsigned int tot = 0u;
        #pragma unroll
        for (int j = 0; j < 8; j++) tot += cc[j];
        unsigned int ti = tot;
        #pragma unroll
        for (int d = 1; d < 32; d <<= 1) {
            unsigned int v = __shfl_up_sync(0xffffffffu, ti, d);
            if (lane >= d) ti += v;
        }
        unsigned int run = ti - tot;               // exclusive prefix
        #pragma unroll
        for (int j = 0; j < 8; j++) {
            unsigned int G = run, E = run + cc[j];
            if (G < K4 && E >= K1) {
                unsigned int w = ((unsigned int)(lane * 8 + j) << 16) | G;
                if (G < K1 && E >= K1) bbs[wrow].x = w;
                if (G < K2 && E >= K2) bbs[wrow].y = w;
                if (G < K3 && E >= K3) bbs[wrow].z = w;
                if (G < K4 && E >= K4) bbs[wrow].w = w;
            }
            run = E;
        }
    }
    __syncwarp();

    const uint4 B = bbs[wrow];
    const unsigned int bk1 = B.x >> 16, bk2 = B.y >> 16, bk3 = B.z >> 16, bk4 = B.w >> 16;
    const unsigned int gg1 = B.x & 0xFFFFu, gg2 = B.y & 0xFFFFu,
                       gg3 = B.z & 0xFFFFu, gg4 = B.w & 0xFFFFu;
    // Fast-path edges: bin < b_k  <=>  min(y,YHI) > E_k  (exact; bin==b_k amb)
    const float E1 = __uint_as_float(TOPB - bk1);
    const float E2 = __uint_as_float(TOPB - bk2);
    const float E3 = __uint_as_float(TOPB - bk3);
    const float E4 = __uint_as_float(TOPB - bk4);
    // exp-domain edges for the write pass: non-amb elems are >= 1/256 in x
    // from the bin edge -> >=0.39% relative margin in e (>> MUFU 2-ulp).
    const float F1 = __expf(E1 - OFFF);
    const float F2 = __expf(E2 - OFFF);
    const float F3 = __expf(E3 - OFFF);
    const float F4 = __expf(E4 - OFFF);

    // ---- vectorized amb detection (bin byte == some boundary bin) ----
    unsigned int ambm = 0u;
    {
        const unsigned int k1x4 = bk1 * 0x01010101u;
        const unsigned int k2x4 = bk2 * 0x01010101u;
        const unsigned int k3x4 = bk3 * 0x01010101u;
        const unsigned int k4x4 = bk4 * 0x01010101u;
        #pragma unroll
        for (int g = 0; g < 4; g++) {
            unsigned int w = binw[g];
            unsigned int z = ZB(w ^ k1x4) | ZB(w ^ k2x4) | ZB(w ^ k3x4) | ZB(w ^ k4x4);
            ambm |= ((((z >> 7) * 0x01020408u) >> 24) & 0xFu) << (4 * g);
        }
    }

    // ---- gather boundary candidates (x live in X; ~6 per row) ----
    {
        const float* xv = (const float*)X;
        unsigned int am = ambm;
        while (am) {
            int i = __ffs(am) - 1; am &= am - 1;
            int gidx = 4 * lane + 128 * (i >> 2) + (i & 3);
            unsigned int b = (binw[i >> 2] >> (8 * (i & 3))) & 255u;
            unsigned long long key = ((unsigned long long)b << 48)
                | ((unsigned long long)mono_key(xv[i]) << 16)
                | (unsigned long long)(65535u - (unsigned int)gidx);
            unsigned int pos = atomicAdd(&listN[wrow], 1u);
            list[wrow][pos] = key;
        }
    }
    __syncwarp();

    // ---- selection: exact rank per candidate -> membership bits + sum deltas ----
    float s1 = 0.f, s2 = 0.f, s3 = 0.f, s4 = 0.f;
    {
        const unsigned int M = listN[wrow];
        for (unsigned int j = lane; j < M; j += 32) {
            unsigned long long cj = list[wrow][j];
            unsigned int hb = (unsigned int)(cj >> 48);
            unsigned int g0 = (hb == bk1) ? gg1 : (hb == bk2) ? gg2
                            : (hb == bk3) ? gg3 : gg4;
            unsigned int r = g0;
            for (unsigned int q = 0u; q < M; q++) {
                unsigned long long cq = list[wrow][q];
                r += (unsigned int)((cq > cj) && ((unsigned int)(cq >> 48) == hb));
            }
            // recover x and exp from the key (exact bit inverse of mono_key)
            unsigned int mk = (unsigned int)(cj >> 16);
            float x = __uint_as_float((mk & 0x80000000u) ? (mk & 0x7FFFFFFFu) : ~mk);
            float e = __expf(x);
            // full membership for all 4 masks from (hb, r)
            bool i1 = (hb < bk1) | ((hb == bk1) & (r < K1));
            bool i2 = (hb < bk2) | ((hb == bk2) & (r < K2));
            bool i3 = (hb < bk3) | ((hb == bk3) & (r < K3));
            bool i4 = (hb < bk4) | ((hb == bk4) & (r < K4));
            // fused fast path contributes 0 for bin==b_k elems -> add-only deltas
            if ((hb == bk1) & (r < K1)) s1 += e;
            if ((hb == bk2) & (r < K2)) s2 += e;
            if ((hb == bk3) & (r < K3)) s3 += e;
            if ((hb == bk4) & (r < K4)) s4 += e;
            unsigned int gidx = 65535u - (unsigned int)(cj & 0xFFFFu);
            ovr[wrow][gidx] = (unsigned char)((unsigned)i1 | ((unsigned)i2 << 1)
                            | ((unsigned)i3 << 2) | ((unsigned)i4 << 3));
        }
    }
    __syncwarp();

    // ---- fused pass: exp + membership sums; X := exp(x).
    //      min(y,YHI) makes the fast path exactly 0 for clamped-high elems
    //      even if bin 0 were a boundary bin (adversarial). Low side safe. ----
    {
        float* xv = (float*)X;
        #pragma unroll
        for (int i = 0; i < 16; i++) {
            float x = xv[i];
            float y = fminf(x + OFFF, YHI);
            float e = __expf(x);          // softmax shift-invariant; |x| ~ 5
            xv[i] = e;
            if (y > E1) s1 += e;
            if (y > E2) s2 += e;
            if (y > E3) s3 += e;
            if (y > E4) s4 += e;
        }
    }
    #pragma unroll
    for (int o = 16; o > 0; o >>= 1) {
        s1 += __shfl_xor_sync(0xffffffffu, s1, o);
        s2 += __shfl_xor_sync(0xffffffffu, s2, o);
        s3 += __shfl_xor_sync(0xffffffffu, s3, o);
        s4 += __shfl_xor_sync(0xffffffffu, s4, o);
    }
    const float q1 = __fdividef(w1, s1), q2 = __fdividef(w2, s2),
                q3 = __fdividef(w3, s3), q4 = __fdividef(w4, s4);

    // ---- write: exp-domain compares (exact for all non-amb elements;
    //      amb elements rewritten below) ----
    {
        const float* ev = (const float*)X;
        float4* op = (float4*)(out + (size_t)row * C);
        #pragma unroll
        for (int g = 0; g < 4; g++) {
            float4 o4;
            float* o = (float*)&o4;
            #pragma unroll
            for (int e = 0; e < 4; e++) {
                float ee = ev[4 * g + e];
                float coef = 0.f;
                if (ee > F1) coef += q1;
                if (ee > F2) coef += q2;
                if (ee > F3) coef += q3;
                if (ee > F4) coef += q4;
                o[e] = ee * coef;
            }
            op[lane + 32 * g] = o4;
        }
    }

    // ---- post-store exact fix for ambiguous elems (1 LDS byte each;
    //      same-thread same-address STG ordering is program order) ----
    if (ambm) {
        const float* ev = (const float*)X;
        float* ob = out + (size_t)row * C;
        unsigned int am = ambm;
        while (am) {
            int i = __ffs(am) - 1; am &= am - 1;
            int gidx = 4 * lane + 128 * (i >> 2) + (i & 3);
            unsigned int bits = ovr[wrow][gidx];
            float cf = 0.f;
            if (bits & 1u) cf += q1;
            if (bits & 2u) cf += q2;
            if (bits & 4u) cf += q3;
            if (bits & 8u) cf += q4;
            ob[gidx] = ev[i] * cf;
        }
    }
}

extern "C" void kernel_launch(void* const* d_in, const int* in_sizes, int n_in,
                              void* d_out, int out_size)
{
    const float* attn = (const float*)d_in[0];
    const float* w1   = (const float*)d_in[1];
    const float* w2   = (const float*)d_in[2];
    const float* w3   = (const float*)d_in[3];
    const float* w4   = (const float*)d_in[4];
    float* out = (float*)d_out;

    int rows   = in_sizes[0] / C;
    int blocks = rows / RPB;
    multiscale_topk_kernel<<<blocks, 32 * RPB>>>(attn, w1, w2, w3, w4, out);
}